// round 2
// baseline (speedup 1.0000x reference)
#include <cuda_runtime.h>
#include <math.h>

// Problem constants (fixed by the dataset)
#define EN 800000
#define QN 50000
#define DD 128
#define NB_SCAN ((QN + 1023) / 1024)   // 49

// -------- scratch (__device__ globals; no allocation allowed) --------
__device__ __align__(16) float g_M[DD * DD];     // Wq @ Wk^T
__device__ __align__(16) float g_r[DD];          // Wk @ bq
__device__ __align__(16) float g_v[DD];          // Wq @ bk
__device__ float g_s0;                            // bk . bq
__device__ __align__(16) float g_z[QN * DD];     // queries @ M + r
__device__ float g_c[QN];                        // queries . v + s0
__device__ float g_probs[EN];
__device__ float g_probs_s[EN];                  // segment-sorted probs
__device__ int   g_eid[EN];                      // segment-sorted edge ids
__device__ int   g_count[QN];
__device__ int   g_start[QN + 1];
__device__ int   g_cursor[QN];
__device__ int   g_blocksum[64];
__device__ int   g_blockbase[64];

// -------- zero the histogram (must run every replay) --------
__global__ void k_zero_counts() {
    int i = blockIdx.x * blockDim.x + threadIdx.x;
    if (i < QN) g_count[i] = 0;
}

// -------- precompute folded weights: M, r, v, s0 --------
__global__ void k_pre(const float* __restrict__ Wq, const float* __restrict__ bq,
                      const float* __restrict__ Wk, const float* __restrict__ bk) {
    if (blockIdx.x == 64) {
        int t = threadIdx.x;
        if (t < DD) {
            float rr = 0.f, vv = 0.f;
            for (int j = 0; j < DD; j++) {
                rr += Wk[t * DD + j] * bq[j];
                vv += Wq[t * DD + j] * bk[j];
            }
            g_r[t] = rr;
            g_v[t] = vv;
            if (t == 0) {
                float s = 0.f;
                for (int j = 0; j < DD; j++) s += bk[j] * bq[j];
                g_s0 = s;
            }
        }
        return;
    }
    int o = blockIdx.x * 256 + threadIdx.x;   // 0..16383
    int t = o >> 7;          // row of Wq
    int i = o & 127;         // row of Wk
    float acc = 0.f;
    for (int j = 0; j < DD; j++) acc += Wq[t * DD + j] * Wk[i * DD + j];
    g_M[t * DD + i] = acc;
}

// -------- z = queries @ M + r ; c = queries . v + s0 --------
// 256 threads, 64 queries x 128 outputs per block, 4x8 register tile per thread.
#define QT 64
#define KC 32
__global__ void __launch_bounds__(256) k_z(const float* __restrict__ queries) {
    __shared__ float sQ[KC][QT];     // transposed: sQ[k][q]
    __shared__ float sM[KC][DD];
    __shared__ float sV[KC];
    int tid = threadIdx.x;
    int qg = tid >> 4;     // 0..15 -> 4 queries each
    int ng = tid & 15;     // 0..15 -> 8 outputs each
    int q0 = blockIdx.x * QT;

    float acc[4][8];
#pragma unroll
    for (int a = 0; a < 4; a++)
#pragma unroll
        for (int b = 0; b < 8; b++) acc[a][b] = 0.f;
    float cacc[4] = {0.f, 0.f, 0.f, 0.f};

    for (int kc = 0; kc < DD; kc += KC) {
        __syncthreads();
        // stage queries tile (transposed)
#pragma unroll
        for (int r = 0; r < 2; r++) {
            int fidx = r * 256 + tid;          // 0..511 float4s
            int ql = fidx >> 3;                // 0..63
            int k4 = fidx & 7;                 // 0..7
            float4 f = make_float4(0.f, 0.f, 0.f, 0.f);
            if (q0 + ql < QN)
                f = *(const float4*)&queries[(q0 + ql) * DD + kc + k4 * 4];
            sQ[k4 * 4 + 0][ql] = f.x;
            sQ[k4 * 4 + 1][ql] = f.y;
            sQ[k4 * 4 + 2][ql] = f.z;
            sQ[k4 * 4 + 3][ql] = f.w;
        }
        // stage M tile
#pragma unroll
        for (int r = 0; r < 4; r++) {
            int fidx = r * 256 + tid;          // 0..1023 float4s
            int row = fidx >> 5;               // 0..31
            int c4 = fidx & 31;                // 0..31
            *(float4*)&sM[row][c4 * 4] = *(const float4*)&g_M[(kc + row) * DD + c4 * 4];
        }
        if (tid < KC) sV[tid] = g_v[kc + tid];
        __syncthreads();

#pragma unroll
        for (int kk = 0; kk < KC; kk++) {
            float4 qv = *(float4*)&sQ[kk][qg * 4];
            float4 m0 = *(float4*)&sM[kk][ng * 8];
            float4 m1 = *(float4*)&sM[kk][ng * 8 + 4];
            float vv = sV[kk];
            float qa[4] = {qv.x, qv.y, qv.z, qv.w};
            float mb[8] = {m0.x, m0.y, m0.z, m0.w, m1.x, m1.y, m1.z, m1.w};
#pragma unroll
            for (int a = 0; a < 4; a++) {
#pragma unroll
                for (int b = 0; b < 8; b++) acc[a][b] += qa[a] * mb[b];
                cacc[a] += qa[a] * vv;
            }
        }
    }

    int n0 = ng * 8;
    float4 r0 = *(const float4*)&g_r[n0];
    float4 r1 = *(const float4*)&g_r[n0 + 4];
    float s0v = g_s0;
#pragma unroll
    for (int a = 0; a < 4; a++) {
        int q = q0 + qg * 4 + a;
        if (q < QN) {
            float4 o0 = make_float4(acc[a][0] + r0.x, acc[a][1] + r0.y,
                                    acc[a][2] + r0.z, acc[a][3] + r0.w);
            float4 o1 = make_float4(acc[a][4] + r1.x, acc[a][5] + r1.y,
                                    acc[a][6] + r1.z, acc[a][7] + r1.w);
            *(float4*)&g_z[q * DD + n0] = o0;
            *(float4*)&g_z[q * DD + n0 + 4] = o1;
            if (ng == 0) g_c[q] = cacc[a] + s0v;
        }
    }
}

// -------- probs[e] = (SV[e] . z[idx[e]] + c[idx[e]]) * scale ; histogram --------
__global__ void k_probs(const float* __restrict__ sv, const int* __restrict__ idx) {
    int warp = (blockIdx.x * blockDim.x + threadIdx.x) >> 5;
    int lane = threadIdx.x & 31;
    int nwarp = (gridDim.x * blockDim.x) >> 5;
    const float scale = 0.0883883476483184f;  // 128^-0.5
    const float4* sv4 = (const float4*)sv;
    const float4* z4 = (const float4*)g_z;
    for (int e = warp; e < EN; e += nwarp) {
        int q = idx[e];
        float4 a = sv4[e * 32 + lane];
        float4 b = z4[q * 32 + lane];
        float d = a.x * b.x + a.y * b.y + a.z * b.z + a.w * b.w;
#pragma unroll
        for (int off = 16; off >= 1; off >>= 1)
            d += __shfl_xor_sync(0xffffffffu, d, off);
        if (lane == 0) {
            g_probs[e] = (d + g_c[q]) * scale;
            atomicAdd(&g_count[q], 1);
        }
    }
}

// -------- exclusive scan of counts (3 small kernels) --------
__global__ void k_scan1() {
    __shared__ int s[1024];
    int tid = threadIdx.x;
    int g = blockIdx.x * 1024 + tid;
    int val = (g < QN) ? g_count[g] : 0;
    s[tid] = val;
    __syncthreads();
    for (int off = 1; off < 1024; off <<= 1) {
        int t = (tid >= off) ? s[tid - off] : 0;
        __syncthreads();
        s[tid] += t;
        __syncthreads();
    }
    if (g < QN) g_start[g] = s[tid] - val;   // exclusive within block
    if (tid == 1023) g_blocksum[blockIdx.x] = s[1023];
}

__global__ void k_scan2() {
    if (threadIdx.x == 0) {
        int run = 0;
        for (int b = 0; b < NB_SCAN; b++) {
            g_blockbase[b] = run;
            run += g_blocksum[b];
        }
    }
}

__global__ void k_scan3() {
    int g = blockIdx.x * 1024 + threadIdx.x;
    if (g < QN) {
        int v = g_start[g] + g_blockbase[blockIdx.x];
        g_start[g] = v;
        g_cursor[g] = v;
    }
    if (g == 0) g_start[QN] = EN;
}

// -------- scatter edges into segment-contiguous order --------
__global__ void k_fill(const int* __restrict__ idx) {
    int e = blockIdx.x * blockDim.x + threadIdx.x;
    if (e < EN) {
        int q = idx[e];
        int pos = atomicAdd(&g_cursor[q], 1);
        g_eid[pos] = e;
        g_probs_s[pos] = g_probs[e];
    }
}

// -------- per-segment softmax + weighted gather-sum (warp per segment) --------
__global__ void k_gather(const float* __restrict__ sv,
                         float* __restrict__ scores, float* __restrict__ attn) {
    int warp = (blockIdx.x * blockDim.x + threadIdx.x) >> 5;
    int lane = threadIdx.x & 31;
    int nwarp = (gridDim.x * blockDim.x) >> 5;
    const float4* sv4 = (const float4*)sv;
    for (int q = warp; q < QN; q += nwarp) {
        int s0 = g_start[q];
        int s1 = g_start[q + 1];
        // segment max
        float m = -INFINITY;
        for (int j = s0 + lane; j < s1; j += 32) m = fmaxf(m, g_probs_s[j]);
#pragma unroll
        for (int off = 16; off >= 1; off >>= 1)
            m = fmaxf(m, __shfl_xor_sync(0xffffffffu, m, off));
        // segment sum of exp
        float ssum = 0.f;
        for (int j = s0 + lane; j < s1; j += 32) ssum += expf(g_probs_s[j] - m);
#pragma unroll
        for (int off = 16; off >= 1; off >>= 1)
            ssum += __shfl_xor_sync(0xffffffffu, ssum, off);
        float inv = (s1 > s0) ? (1.0f / ssum) : 0.f;

        float4 acc = make_float4(0.f, 0.f, 0.f, 0.f);
        // 2-way software pipeline over edges for MLP
        int j = s0;
        for (; j + 1 < s1; j += 2) {
            int e0 = g_eid[j];
            int e1 = g_eid[j + 1];
            float p0 = g_probs_s[j];
            float p1 = g_probs_s[j + 1];
            float4 a0 = sv4[e0 * 32 + lane];
            float4 a1 = sv4[e1 * 32 + lane];
            float sc0 = expf(p0 - m) * inv;
            float sc1 = expf(p1 - m) * inv;
            if (lane == 0) { scores[e0] = sc0; scores[e1] = sc1; }
            acc.x += sc0 * a0.x + sc1 * a1.x;
            acc.y += sc0 * a0.y + sc1 * a1.y;
            acc.z += sc0 * a0.z + sc1 * a1.z;
            acc.w += sc0 * a0.w + sc1 * a1.w;
        }
        if (j < s1) {
            int e0 = g_eid[j];
            float sc0 = expf(g_probs_s[j] - m) * inv;
            if (lane == 0) scores[e0] = sc0;
            float4 a0 = sv4[e0 * 32 + lane];
            acc.x += sc0 * a0.x;
            acc.y += sc0 * a0.y;
            acc.z += sc0 * a0.z;
            acc.w += sc0 * a0.w;
        }
        ((float4*)attn)[q * 32 + lane] = acc;
    }
}

// -------- launcher --------
// inputs (metadata order): scattered_values [E,D] f32, indices [E] i32,
// queries [Q,D] f32, Wq [D,D], bq [D], Wk [D,D], bk [D]
// output: scores [E] then attn_applied [Q,D], fp32, concatenated.
extern "C" void kernel_launch(void* const* d_in, const int* in_sizes, int n_in,
                              void* d_out, int out_size) {
    const float* sv      = (const float*)d_in[0];
    const int*   idx     = (const int*)d_in[1];
    const float* queries = (const float*)d_in[2];
    const float* Wq      = (const float*)d_in[3];
    const float* bq      = (const float*)d_in[4];
    const float* Wk      = (const float*)d_in[5];
    const float* bk      = (const float*)d_in[6];
    float* scores = (float*)d_out;
    float* attn   = (float*)d_out + EN;

    k_zero_counts<<<(QN + 255) / 256, 256>>>();
    k_pre<<<65, 256>>>(Wq, bq, Wk, bk);
    k_z<<<(QN + QT - 1) / QT, 256>>>(queries);
    k_probs<<<4096, 256>>>(sv, idx);
    k_scan1<<<NB_SCAN, 1024>>>();
    k_scan2<<<1, 32>>>();
    k_scan3<<<NB_SCAN, 1024>>>();
    k_fill<<<(EN + 255) / 256, 256>>>(idx);
    k_gather<<<2048, 256>>>(sv, scores, attn);
}

// round 5
// speedup vs baseline: 1.7570x; 1.7570x over previous
#include <cuda_runtime.h>
#include <math.h>

// Problem constants (fixed by the dataset)
#define EN 800000
#define QN 50000
#define DD 128
#define NB_SCAN ((QN + 1023) / 1024)   // 49
#define CAP 192                        // per-warp prob cache (segments > CAP use slow path)

// -------- scratch (__device__ globals; no allocation allowed) --------
__device__ __align__(16) float g_M[DD * DD];     // Wq @ Wk^T
__device__ __align__(16) float g_r[DD];          // Wk @ bq
__device__ __align__(16) float g_v[DD];          // Wq @ bk
__device__ float g_s0;                            // bk . bq
__device__ __align__(16) float g_z[QN * DD];     // queries @ M + r
__device__ float g_c[QN];                        // queries . v + s0
__device__ int   g_eid[EN];                      // segment-sorted edge ids
__device__ int   g_count[QN];
__device__ int   g_start[QN + 1];
__device__ int   g_cursor[QN];
__device__ int   g_blocksum[64];
__device__ int   g_blockbase[64];

// -------- zero the histogram (must run every replay) --------
__global__ void k_zero_counts() {
    int i = blockIdx.x * blockDim.x + threadIdx.x;
    if (i < QN) g_count[i] = 0;
}

// -------- histogram of indices --------
__global__ void k_hist(const int* __restrict__ idx) {
    int i = blockIdx.x * blockDim.x + threadIdx.x;
    int n = gridDim.x * blockDim.x;
    for (int e = i; e < EN; e += n) atomicAdd(&g_count[idx[e]], 1);
}

// -------- precompute folded weights: M, r, v, s0 --------
__global__ void k_pre(const float* __restrict__ Wq, const float* __restrict__ bq,
                      const float* __restrict__ Wk, const float* __restrict__ bk) {
    if (blockIdx.x == 64) {
        int t = threadIdx.x;
        if (t < DD) {
            float rr = 0.f, vv = 0.f;
            for (int j = 0; j < DD; j++) {
                rr += Wk[t * DD + j] * bq[j];
                vv += Wq[t * DD + j] * bk[j];
            }
            g_r[t] = rr;
            g_v[t] = vv;
            if (t == 0) {
                float s = 0.f;
                for (int j = 0; j < DD; j++) s += bk[j] * bq[j];
                g_s0 = s;
            }
        }
        return;
    }
    int o = blockIdx.x * 256 + threadIdx.x;   // 0..16383
    int t = o >> 7;          // row of Wq
    int i = o & 127;         // row of Wk
    float acc = 0.f;
    for (int j = 0; j < DD; j++) acc += Wq[t * DD + j] * Wk[i * DD + j];
    g_M[t * DD + i] = acc;
}

// -------- z = queries @ M + r ; c = queries . v + s0 --------
#define QT 64
#define KC 32
__global__ void __launch_bounds__(256) k_z(const float* __restrict__ queries) {
    __shared__ float sQ[KC][QT];     // transposed: sQ[k][q]
    __shared__ float sM[KC][DD];
    __shared__ float sV[KC];
    int tid = threadIdx.x;
    int qg = tid >> 4;     // 0..15 -> 4 queries each
    int ng = tid & 15;     // 0..15 -> 8 outputs each
    int q0 = blockIdx.x * QT;

    float acc[4][8];
#pragma unroll
    for (int a = 0; a < 4; a++)
#pragma unroll
        for (int b = 0; b < 8; b++) acc[a][b] = 0.f;
    float cacc[4] = {0.f, 0.f, 0.f, 0.f};

    for (int kc = 0; kc < DD; kc += KC) {
        __syncthreads();
#pragma unroll
        for (int r = 0; r < 2; r++) {
            int fidx = r * 256 + tid;          // 0..511 float4s
            int ql = fidx >> 3;                // 0..63
            int k4 = fidx & 7;                 // 0..7
            float4 f = make_float4(0.f, 0.f, 0.f, 0.f);
            if (q0 + ql < QN)
                f = *(const float4*)&queries[(q0 + ql) * DD + kc + k4 * 4];
            sQ[k4 * 4 + 0][ql] = f.x;
            sQ[k4 * 4 + 1][ql] = f.y;
            sQ[k4 * 4 + 2][ql] = f.z;
            sQ[k4 * 4 + 3][ql] = f.w;
        }
#pragma unroll
        for (int r = 0; r < 4; r++) {
            int fidx = r * 256 + tid;          // 0..1023 float4s
            int row = fidx >> 5;               // 0..31
            int c4 = fidx & 31;                // 0..31
            *(float4*)&sM[row][c4 * 4] = *(const float4*)&g_M[(kc + row) * DD + c4 * 4];
        }
        if (tid < KC) sV[tid] = g_v[kc + tid];
        __syncthreads();

#pragma unroll
        for (int kk = 0; kk < KC; kk++) {
            float4 qv = *(float4*)&sQ[kk][qg * 4];
            float4 m0 = *(float4*)&sM[kk][ng * 8];
            float4 m1 = *(float4*)&sM[kk][ng * 8 + 4];
            float vv = sV[kk];
            float qa[4] = {qv.x, qv.y, qv.z, qv.w};
            float mb[8] = {m0.x, m0.y, m0.z, m0.w, m1.x, m1.y, m1.z, m1.w};
#pragma unroll
            for (int a = 0; a < 4; a++) {
#pragma unroll
                for (int b = 0; b < 8; b++) acc[a][b] += qa[a] * mb[b];
                cacc[a] += qa[a] * vv;
            }
        }
    }

    int n0 = ng * 8;
    float4 r0 = *(const float4*)&g_r[n0];
    float4 r1 = *(const float4*)&g_r[n0 + 4];
    float s0v = g_s0;
#pragma unroll
    for (int a = 0; a < 4; a++) {
        int q = q0 + qg * 4 + a;
        if (q < QN) {
            float4 o0 = make_float4(acc[a][0] + r0.x, acc[a][1] + r0.y,
                                    acc[a][2] + r0.z, acc[a][3] + r0.w);
            float4 o1 = make_float4(acc[a][4] + r1.x, acc[a][5] + r1.y,
                                    acc[a][6] + r1.z, acc[a][7] + r1.w);
            *(float4*)&g_z[q * DD + n0] = o0;
            *(float4*)&g_z[q * DD + n0 + 4] = o1;
            if (ng == 0) g_c[q] = cacc[a] + s0v;
        }
    }
}

// -------- exclusive scan of counts --------
__global__ void k_scan1() {
    __shared__ int s[1024];
    int tid = threadIdx.x;
    int g = blockIdx.x * 1024 + tid;
    int val = (g < QN) ? g_count[g] : 0;
    s[tid] = val;
    __syncthreads();
    for (int off = 1; off < 1024; off <<= 1) {
        int t = (tid >= off) ? s[tid - off] : 0;
        __syncthreads();
        s[tid] += t;
        __syncthreads();
    }
    if (g < QN) g_start[g] = s[tid] - val;
    if (tid == 1023) g_blocksum[blockIdx.x] = s[1023];
}

__global__ void k_scan2() {
    if (threadIdx.x == 0) {
        int run = 0;
        for (int b = 0; b < NB_SCAN; b++) {
            g_blockbase[b] = run;
            run += g_blocksum[b];
        }
    }
}

__global__ void k_scan3() {
    int g = blockIdx.x * 1024 + threadIdx.x;
    if (g < QN) {
        int v = g_start[g] + g_blockbase[blockIdx.x];
        g_start[g] = v;
        g_cursor[g] = v;
    }
    if (g == 0) g_start[QN] = EN;
}

// -------- scatter edge ids into segment-contiguous order --------
__global__ void k_fill(const int* __restrict__ idx) {
    int e = blockIdx.x * blockDim.x + threadIdx.x;
    if (e < EN) {
        int q = idx[e];
        int pos = atomicAdd(&g_cursor[q], 1);
        g_eid[pos] = e;
    }
}

// -------- fused: probs + segment softmax + weighted gather-sum --------
// Warp per segment. Pass 1 computes probs (SV from DRAM, z row in registers),
// caches them in smem; pass 2 re-reads SV rows (L2 hit) for the weighted sum.
__device__ __forceinline__ float warp_red_sum(float d) {
#pragma unroll
    for (int off = 16; off >= 1; off >>= 1)
        d += __shfl_xor_sync(0xffffffffu, d, off);
    return d;
}

__global__ void __launch_bounds__(256) k_fused(const float* __restrict__ sv,
                                               float* __restrict__ scores,
                                               float* __restrict__ attn) {
    __shared__ float sP[8][CAP];
    int w = threadIdx.x >> 5;
    int lane = threadIdx.x & 31;
    int q = blockIdx.x * 8 + w;
    if (q >= QN) return;

    const float4* sv4 = (const float4*)sv;
    const float scale = 0.0883883476483184f;  // 128^-0.5

    int s0 = g_start[q];
    int s1 = g_start[q + 1];

    // z row + c for this segment (coalesced: q is block-sequential)
    float4 zr = ((const float4*)g_z)[q * 32 + lane];
    float cq = g_c[q];

    // ---- pass 1: probs, running max ----
    float m = -INFINITY;
    int j = s0;
    for (; j + 3 < s1; j += 4) {
        int e0 = g_eid[j], e1 = g_eid[j + 1], e2 = g_eid[j + 2], e3 = g_eid[j + 3];
        float4 a0 = sv4[e0 * 32 + lane];
        float4 a1 = sv4[e1 * 32 + lane];
        float4 a2 = sv4[e2 * 32 + lane];
        float4 a3 = sv4[e3 * 32 + lane];
        float d0 = a0.x * zr.x + a0.y * zr.y + a0.z * zr.z + a0.w * zr.w;
        float d1 = a1.x * zr.x + a1.y * zr.y + a1.z * zr.z + a1.w * zr.w;
        float d2 = a2.x * zr.x + a2.y * zr.y + a2.z * zr.z + a2.w * zr.w;
        float d3 = a3.x * zr.x + a3.y * zr.y + a3.z * zr.z + a3.w * zr.w;
#pragma unroll
        for (int off = 16; off >= 1; off >>= 1) {
            d0 += __shfl_xor_sync(0xffffffffu, d0, off);
            d1 += __shfl_xor_sync(0xffffffffu, d1, off);
            d2 += __shfl_xor_sync(0xffffffffu, d2, off);
            d3 += __shfl_xor_sync(0xffffffffu, d3, off);
        }
        float p0 = (d0 + cq) * scale;
        float p1 = (d1 + cq) * scale;
        float p2 = (d2 + cq) * scale;
        float p3 = (d3 + cq) * scale;
        m = fmaxf(m, fmaxf(fmaxf(p0, p1), fmaxf(p2, p3)));
        int o = j - s0;
        if (o + 4 <= CAP && lane < 4) {
            float pk = (lane == 0) ? p0 : (lane == 1) ? p1 : (lane == 2) ? p2 : p3;
            sP[w][o + lane] = pk;
        }
    }
    for (; j < s1; j++) {
        int e = g_eid[j];
        float4 a = sv4[e * 32 + lane];
        float d = warp_red_sum(a.x * zr.x + a.y * zr.y + a.z * zr.z + a.w * zr.w);
        float p = (d + cq) * scale;
        m = fmaxf(m, p);
        int o = j - s0;
        if (o < CAP && lane == 0) sP[w][o] = p;
    }
    __syncwarp();

    // ---- segment sum of exp ----
    int cnt = s1 - s0;
    int stored = cnt < CAP ? cnt : CAP;
    float ssum = 0.f;
    for (int t = lane; t < stored; t += 32) ssum += __expf(sP[w][t] - m);
    // rare overflow path: recompute dot for edges beyond CAP
    for (int jo = s0 + CAP; jo < s1; jo++) {
        int e = g_eid[jo];
        float4 a = sv4[e * 32 + lane];
        float d = warp_red_sum(a.x * zr.x + a.y * zr.y + a.z * zr.z + a.w * zr.w);
        if (lane == 0) ssum += __expf((d + cq) * scale - m);
    }
    ssum = warp_red_sum(ssum);
    float inv = (cnt > 0) ? (1.0f / ssum) : 0.f;

    // ---- pass 2: scores + weighted sum (SV rows now in L2) ----
    float4 acc = make_float4(0.f, 0.f, 0.f, 0.f);
    int lim = s0 + stored;
    j = s0;
    for (; j + 3 < lim; j += 4) {
        int o = j - s0;
        int e0 = g_eid[j], e1 = g_eid[j + 1], e2 = g_eid[j + 2], e3 = g_eid[j + 3];
        float sc0 = __expf(sP[w][o] - m) * inv;
        float sc1 = __expf(sP[w][o + 1] - m) * inv;
        float sc2 = __expf(sP[w][o + 2] - m) * inv;
        float sc3 = __expf(sP[w][o + 3] - m) * inv;
        float4 a0 = sv4[e0 * 32 + lane];
        float4 a1 = sv4[e1 * 32 + lane];
        float4 a2 = sv4[e2 * 32 + lane];
        float4 a3 = sv4[e3 * 32 + lane];
        if (lane == 0) {
            scores[e0] = sc0; scores[e1] = sc1; scores[e2] = sc2; scores[e3] = sc3;
        }
        acc.x += sc0 * a0.x + sc1 * a1.x + sc2 * a2.x + sc3 * a3.x;
        acc.y += sc0 * a0.y + sc1 * a1.y + sc2 * a2.y + sc3 * a3.y;
        acc.z += sc0 * a0.z + sc1 * a1.z + sc2 * a2.z + sc3 * a3.z;
        acc.w += sc0 * a0.w + sc1 * a1.w + sc2 * a2.w + sc3 * a3.w;
    }
    for (; j < lim; j++) {
        int e = g_eid[j];
        float sc = __expf(sP[w][j - s0] - m) * inv;
        float4 a = sv4[e * 32 + lane];
        if (lane == 0) scores[e] = sc;
        acc.x += sc * a.x; acc.y += sc * a.y; acc.z += sc * a.z; acc.w += sc * a.w;
    }
    // rare overflow path
    for (int jo = s0 + CAP; jo < s1; jo++) {
        int e = g_eid[jo];
        float4 a = sv4[e * 32 + lane];
        float d = warp_red_sum(a.x * zr.x + a.y * zr.y + a.z * zr.z + a.w * zr.w);
        float sc = __expf((d + cq) * scale - m) * inv;
        if (lane == 0) scores[e] = sc;
        acc.x += sc * a.x; acc.y += sc * a.y; acc.z += sc * a.z; acc.w += sc * a.w;
    }

    ((float4*)attn)[q * 32 + lane] = acc;
}

// -------- launcher --------
// inputs (metadata order): scattered_values [E,D] f32, indices [E] i32,
// queries [Q,D] f32, Wq [D,D], bq [D], Wk [D,D], bk [D]
// output: scores [E] then attn_applied [Q,D], fp32, concatenated.
extern "C" void kernel_launch(void* const* d_in, const int* in_sizes, int n_in,
                              void* d_out, int out_size) {
    const float* sv      = (const float*)d_in[0];
    const int*   idx     = (const int*)d_in[1];
    const float* queries = (const float*)d_in[2];
    const float* Wq      = (const float*)d_in[3];
    const float* bq      = (const float*)d_in[4];
    const float* Wk      = (const float*)d_in[5];
    const float* bk      = (const float*)d_in[6];
    float* scores = (float*)d_out;
    float* attn   = (float*)d_out + EN;

    k_zero_counts<<<(QN + 255) / 256, 256>>>();
    k_pre<<<65, 256>>>(Wq, bq, Wk, bk);
    k_hist<<<1024, 256>>>(idx);
    k_z<<<(QN + QT - 1) / QT, 256>>>(queries);
    k_scan1<<<NB_SCAN, 1024>>>();
    k_scan2<<<1, 32>>>();
    k_scan3<<<NB_SCAN, 1024>>>();
    k_fill<<<(EN + 255) / 256, 256>>>(idx);
    k_fused<<<(QN + 7) / 8, 256>>>(sv, scores, attn);
}

// round 6
// speedup vs baseline: 2.2086x; 1.2570x over previous
#include <cuda_runtime.h>
#include <math.h>

// Problem constants (fixed by the dataset)
#define EN 800000
#define QN 50000
#define DD 128
#define NB_SCAN ((QN + 1023) / 1024)   // 49
#define CAP 160                        // per-warp prob cache (segments > CAP use slow path)

// -------- scratch (__device__ globals; no allocation allowed) --------
__device__ __align__(16) float g_M[DD * DD];     // Wq @ Wk^T
__device__ __align__(16) float g_r[DD];          // Wk @ bq
__device__ __align__(16) float g_v[DD];          // Wq @ bk
__device__ float g_s0;                            // bk . bq
__device__ __align__(16) float g_z[QN * DD];     // (queries @ M + r) * scale
__device__ float g_c[QN];                        // (queries . v + s0) * scale
__device__ int   g_eid[EN];                      // segment-sorted edge ids
__device__ int   g_count[QN];
__device__ int   g_start[QN + 1];
__device__ int   g_cursor[QN];
__device__ int   g_blocksum[64];
__device__ int   g_blockbase[64];

// -------- zero the histogram (must run every replay) --------
__global__ void k_zero_counts() {
    int i = blockIdx.x * blockDim.x + threadIdx.x;
    if (i < QN) g_count[i] = 0;
}

// -------- histogram of indices --------
__global__ void k_hist(const int* __restrict__ idx) {
    int i = blockIdx.x * blockDim.x + threadIdx.x;
    int n = gridDim.x * blockDim.x;
    for (int e = i; e < EN; e += n) atomicAdd(&g_count[idx[e]], 1);
}

// -------- precompute folded weights: M, r, v, s0 --------
__global__ void k_pre(const float* __restrict__ Wq, const float* __restrict__ bq,
                      const float* __restrict__ Wk, const float* __restrict__ bk) {
    if (blockIdx.x == 64) {
        int t = threadIdx.x;
        if (t < DD) {
            float rr = 0.f, vv = 0.f;
            for (int j = 0; j < DD; j++) {
                rr += Wk[t * DD + j] * bq[j];
                vv += Wq[t * DD + j] * bk[j];
            }
            g_r[t] = rr;
            g_v[t] = vv;
            if (t == 0) {
                float s = 0.f;
                for (int j = 0; j < DD; j++) s += bk[j] * bq[j];
                g_s0 = s;
            }
        }
        return;
    }
    int o = blockIdx.x * 256 + threadIdx.x;   // 0..16383
    int t = o >> 7;          // row of Wq
    int i = o & 127;         // row of Wk
    float acc = 0.f;
    for (int j = 0; j < DD; j++) acc += Wq[t * DD + j] * Wk[i * DD + j];
    g_M[t * DD + i] = acc;
}

// -------- z = (queries @ M + r)*scale ; c = (queries . v + s0)*scale --------
// 128x128 block tile, 256 threads, 8x8 register tile, KC=16.
#define ZT 128
#define ZKC 16
__global__ void __launch_bounds__(256) k_z(const float* __restrict__ queries) {
    __shared__ float sQ[ZKC][ZT];     // transposed: sQ[k][row]
    __shared__ float sM[ZKC][DD];
    __shared__ float sV[ZKC];
    int tid = threadIdx.x;
    int tx = tid & 15;                // output-col group (8 cols)
    int ty = tid >> 4;                // row group (8 rows)
    int q0 = blockIdx.x * ZT;

    float acc[8][8];
#pragma unroll
    for (int i = 0; i < 8; i++)
#pragma unroll
        for (int jj = 0; jj < 8; jj++) acc[i][jj] = 0.f;
    float cacc[8] = {0.f, 0.f, 0.f, 0.f, 0.f, 0.f, 0.f, 0.f};

    for (int kc = 0; kc < DD; kc += ZKC) {
        __syncthreads();
        // stage queries tile 128 rows x 16 k (transposed into sQ)
#pragma unroll
        for (int r = 0; r < 2; r++) {
            int fidx = r * 256 + tid;     // 0..511
            int row = fidx >> 2;          // 0..127
            int c4 = fidx & 3;            // 0..3
            float4 f = make_float4(0.f, 0.f, 0.f, 0.f);
            if (q0 + row < QN)
                f = *(const float4*)&queries[(q0 + row) * DD + kc + c4 * 4];
            sQ[c4 * 4 + 0][row] = f.x;
            sQ[c4 * 4 + 1][row] = f.y;
            sQ[c4 * 4 + 2][row] = f.z;
            sQ[c4 * 4 + 3][row] = f.w;
        }
        // stage M tile 16 k-rows x 128 cols
#pragma unroll
        for (int r = 0; r < 2; r++) {
            int fidx = r * 256 + tid;     // 0..511
            int row = fidx >> 5;          // 0..15
            int c4 = fidx & 31;           // 0..31
            *(float4*)&sM[row][c4 * 4] = *(const float4*)&g_M[(kc + row) * DD + c4 * 4];
        }
        if (tid < ZKC) sV[tid] = g_v[kc + tid];
        __syncthreads();

#pragma unroll
        for (int kk = 0; kk < ZKC; kk++) {
            float4 a0 = *(float4*)&sQ[kk][ty * 8];
            float4 a1 = *(float4*)&sQ[kk][ty * 8 + 4];
            float4 b0 = *(float4*)&sM[kk][tx * 8];
            float4 b1 = *(float4*)&sM[kk][tx * 8 + 4];
            float vv = sV[kk];
            float av[8] = {a0.x, a0.y, a0.z, a0.w, a1.x, a1.y, a1.z, a1.w};
            float bv[8] = {b0.x, b0.y, b0.z, b0.w, b1.x, b1.y, b1.z, b1.w};
#pragma unroll
            for (int i = 0; i < 8; i++) {
#pragma unroll
                for (int jj = 0; jj < 8; jj++) acc[i][jj] += av[i] * bv[jj];
                cacc[i] += av[i] * vv;
            }
        }
    }

    const float scale = 0.0883883476483184f;  // 128^-0.5
    int n0 = tx * 8;
    float4 r0 = *(const float4*)&g_r[n0];
    float4 r1 = *(const float4*)&g_r[n0 + 4];
    float s0v = g_s0;
#pragma unroll
    for (int i = 0; i < 8; i++) {
        int q = q0 + ty * 8 + i;
        if (q < QN) {
            float4 o0 = make_float4((acc[i][0] + r0.x) * scale, (acc[i][1] + r0.y) * scale,
                                    (acc[i][2] + r0.z) * scale, (acc[i][3] + r0.w) * scale);
            float4 o1 = make_float4((acc[i][4] + r1.x) * scale, (acc[i][5] + r1.y) * scale,
                                    (acc[i][6] + r1.z) * scale, (acc[i][7] + r1.w) * scale);
            *(float4*)&g_z[q * DD + n0] = o0;
            *(float4*)&g_z[q * DD + n0 + 4] = o1;
            if (tx == 0) g_c[q] = (cacc[i] + s0v) * scale;
        }
    }
}

// -------- exclusive scan of counts --------
__global__ void k_scan1() {
    __shared__ int s[1024];
    int tid = threadIdx.x;
    int g = blockIdx.x * 1024 + tid;
    int val = (g < QN) ? g_count[g] : 0;
    s[tid] = val;
    __syncthreads();
    for (int off = 1; off < 1024; off <<= 1) {
        int t = (tid >= off) ? s[tid - off] : 0;
        __syncthreads();
        s[tid] += t;
        __syncthreads();
    }
    if (g < QN) g_start[g] = s[tid] - val;
    if (tid == 1023) g_blocksum[blockIdx.x] = s[1023];
}

__global__ void k_scan2() {
    if (threadIdx.x == 0) {
        int run = 0;
        for (int b = 0; b < NB_SCAN; b++) {
            g_blockbase[b] = run;
            run += g_blocksum[b];
        }
    }
}

__global__ void k_scan3() {
    int g = blockIdx.x * 1024 + threadIdx.x;
    if (g < QN) {
        int v = g_start[g] + g_blockbase[blockIdx.x];
        g_start[g] = v;
        g_cursor[g] = v;
    }
    if (g == 0) g_start[QN] = EN;
}

// -------- scatter edge ids into segment-contiguous order --------
__global__ void k_fill(const int* __restrict__ idx) {
    int e = blockIdx.x * blockDim.x + threadIdx.x;
    if (e < EN) {
        int q = idx[e];
        int pos = atomicAdd(&g_cursor[q], 1);
        g_eid[pos] = e;
    }
}

// -------- fused single pass: probs + online softmax + weighted gather-sum --------
__device__ __forceinline__ float warp_red_sum(float d) {
#pragma unroll
    for (int off = 16; off >= 1; off >>= 1)
        d += __shfl_xor_sync(0xffffffffu, d, off);
    return d;
}

__global__ void __launch_bounds__(256) k_fused(const float* __restrict__ sv,
                                               float* __restrict__ scores,
                                               float* __restrict__ attn) {
    __shared__ float sP[8][CAP];
    int w = threadIdx.x >> 5;
    int lane = threadIdx.x & 31;
    int q = blockIdx.x * 8 + w;
    if (q >= QN) return;

    const float4* sv4 = (const float4*)sv;
    int s0 = g_start[q];
    int s1 = g_start[q + 1];
    int cnt = s1 - s0;

    // z row (pre-scaled) + c for this segment (coalesced: q is block-sequential)
    float4 zr = ((const float4*)g_z)[q * 32 + lane];
    float cq = g_c[q];

    // ---- single pass: probs + online (m, ssum, acc) ----
    float m = -INFINITY;
    float ssum = 0.f;
    float4 acc = make_float4(0.f, 0.f, 0.f, 0.f);

    int j = s0;
    for (; j + 3 < s1; j += 4) {
        int e0 = g_eid[j], e1 = g_eid[j + 1], e2 = g_eid[j + 2], e3 = g_eid[j + 3];
        float4 a0 = sv4[e0 * 32 + lane];
        float4 a1 = sv4[e1 * 32 + lane];
        float4 a2 = sv4[e2 * 32 + lane];
        float4 a3 = sv4[e3 * 32 + lane];
        float d0 = a0.x * zr.x + a0.y * zr.y + a0.z * zr.z + a0.w * zr.w;
        float d1 = a1.x * zr.x + a1.y * zr.y + a1.z * zr.z + a1.w * zr.w;
        float d2 = a2.x * zr.x + a2.y * zr.y + a2.z * zr.z + a2.w * zr.w;
        float d3 = a3.x * zr.x + a3.y * zr.y + a3.z * zr.z + a3.w * zr.w;
#pragma unroll
        for (int off = 16; off >= 1; off >>= 1) {
            d0 += __shfl_xor_sync(0xffffffffu, d0, off);
            d1 += __shfl_xor_sync(0xffffffffu, d1, off);
            d2 += __shfl_xor_sync(0xffffffffu, d2, off);
            d3 += __shfl_xor_sync(0xffffffffu, d3, off);
        }
        float p0 = d0 + cq, p1 = d1 + cq, p2 = d2 + cq, p3 = d3 + cq;
        int o = j - s0;
        if (o + 4 <= CAP && lane < 4) {
            float pk = (lane == 0) ? p0 : (lane == 1) ? p1 : (lane == 2) ? p2 : p3;
            sP[w][o + lane] = pk;
        }
        float gm = fmaxf(fmaxf(p0, p1), fmaxf(p2, p3));
        if (gm > m) {   // warp-uniform branch
            float f = __expf(m - gm);
            ssum *= f;
            acc.x *= f; acc.y *= f; acc.z *= f; acc.w *= f;
            m = gm;
        }
        float w0 = __expf(p0 - m), w1 = __expf(p1 - m);
        float w2 = __expf(p2 - m), w3 = __expf(p3 - m);
        ssum += (w0 + w1) + (w2 + w3);
        acc.x += w0 * a0.x + w1 * a1.x + w2 * a2.x + w3 * a3.x;
        acc.y += w0 * a0.y + w1 * a1.y + w2 * a2.y + w3 * a3.y;
        acc.z += w0 * a0.z + w1 * a1.z + w2 * a2.z + w3 * a3.z;
        acc.w += w0 * a0.w + w1 * a1.w + w2 * a2.w + w3 * a3.w;
    }
    for (; j < s1; j++) {
        int e = g_eid[j];
        float4 a = sv4[e * 32 + lane];
        float d = warp_red_sum(a.x * zr.x + a.y * zr.y + a.z * zr.z + a.w * zr.w);
        float p = d + cq;
        int o = j - s0;
        if (o < CAP && lane == 0) sP[w][o] = p;
        if (p > m) {
            float f = __expf(m - p);
            ssum *= f;
            acc.x *= f; acc.y *= f; acc.z *= f; acc.w *= f;
            m = p;
        }
        float w0 = __expf(p - m);
        ssum += w0;
        acc.x += w0 * a.x; acc.y += w0 * a.y; acc.z += w0 * a.z; acc.w += w0 * a.w;
    }
    __syncwarp();

    float inv = (cnt > 0) ? (1.0f / ssum) : 0.f;

    // ---- epilogue: scores from cached probs ----
    int stored = cnt < CAP ? cnt : CAP;
    for (int t = lane; t < stored; t += 32)
        scores[g_eid[s0 + t]] = __expf(sP[w][t] - m) * inv;
    // rare overflow path: recompute dot for edges beyond CAP
    for (int jo = s0 + CAP; jo < s1; jo++) {
        int e = g_eid[jo];
        float4 a = sv4[e * 32 + lane];
        float d = warp_red_sum(a.x * zr.x + a.y * zr.y + a.z * zr.z + a.w * zr.w);
        if (lane == 0) scores[e] = __expf(d + cq - m) * inv;
    }

    ((float4*)attn)[q * 32 + lane] =
        make_float4(acc.x * inv, acc.y * inv, acc.z * inv, acc.w * inv);
}

// -------- launcher --------
// inputs (metadata order): scattered_values [E,D] f32, indices [E] i32,
// queries [Q,D] f32, Wq [D,D], bq [D], Wk [D,D], bk [D]
// output: scores [E] then attn_applied [Q,D], fp32, concatenated.
extern "C" void kernel_launch(void* const* d_in, const int* in_sizes, int n_in,
                              void* d_out, int out_size) {
    const float* sv      = (const float*)d_in[0];
    const int*   idx     = (const int*)d_in[1];
    const float* queries = (const float*)d_in[2];
    const float* Wq      = (const float*)d_in[3];
    const float* bq      = (const float*)d_in[4];
    const float* Wk      = (const float*)d_in[5];
    const float* bk      = (const float*)d_in[6];
    float* scores = (float*)d_out;
    float* attn   = (float*)d_out + EN;

    // side stream + events for fork-join (created once, outside any capture;
    // every call performs identical work)
    static cudaStream_t s2 = nullptr;
    static cudaEvent_t evFork = nullptr, evJoin = nullptr;
    if (s2 == nullptr) {
        cudaStreamCreateWithFlags(&s2, cudaStreamNonBlocking);
        cudaEventCreateWithFlags(&evFork, cudaEventDisableTiming);
        cudaEventCreateWithFlags(&evJoin, cudaEventDisableTiming);
    }

    // fork: CSR-build chain on s2, GEMM chain on the main stream
    cudaEventRecord(evFork, 0);
    cudaStreamWaitEvent(s2, evFork, 0);

    k_zero_counts<<<(QN + 255) / 256, 256, 0, s2>>>();
    k_hist<<<1024, 256, 0, s2>>>(idx);
    k_scan1<<<NB_SCAN, 1024, 0, s2>>>();
    k_scan2<<<1, 32, 0, s2>>>();
    k_scan3<<<NB_SCAN, 1024, 0, s2>>>();
    k_fill<<<(EN + 255) / 256, 256, 0, s2>>>(idx);
    cudaEventRecord(evJoin, s2);

    k_pre<<<65, 256>>>(Wq, bq, Wk, bk);
    k_z<<<(QN + ZT - 1) / ZT, 256>>>(queries);

    // join, then the fused pass
    cudaStreamWaitEvent(0, evJoin, 0);
    k_fused<<<(QN + 7) / 8, 256>>>(sv, scores, attn);
}